// round 3
// baseline (speedup 1.0000x reference)
#include <cuda_runtime.h>
#include <cuda_bf16.h>
#include <cstdint>
#include <math_constants.h>

#define T_STEPS 1024
#define DIM     300
#define HD1     1024
#define HD2     512
#define VGLOB   50000
#define VSENS   25000
#define NCTA    148

#define TILES_G 391
#define TILES_S 196
#define PSTR_G  392
#define PSTR_S  200

// ------------------------- device scratch -------------------------
__device__ __align__(16) float g_U1[T_STEPS * HD1];
__device__ __align__(16) float g_h2s[T_STEPS * HD2];
__device__ __align__(16) float g_h1buf[2][HD1];
__device__ __align__(16) float g_h2buf[2][HD2];
__device__ unsigned g_cnt;
__device__ float g_pmaxG[T_STEPS * PSTR_G];
__device__ float g_psumG[T_STEPS * PSTR_G];
__device__ float g_pmaxS[T_STEPS * PSTR_S];
__device__ float g_psumS[T_STEPS * PSTR_S];
__device__ float g_lseG[T_STEPS];
__device__ float g_lseS[T_STEPS];

// ------------------------- helpers -------------------------
__device__ __forceinline__ float to_tf32(float x) {
    uint32_t u;
    asm("cvt.rna.tf32.f32 %0, %1;" : "=r"(u) : "f"(x));
    return __uint_as_float(u);
}

__device__ __forceinline__ void mma_tf32(float c[4], const uint32_t a[4], const uint32_t b[2]) {
    asm volatile(
        "mma.sync.aligned.m16n8k8.row.col.f32.tf32.tf32.f32 "
        "{%0,%1,%2,%3}, {%4,%5,%6,%7}, {%8,%9}, {%0,%1,%2,%3};"
        : "+f"(c[0]), "+f"(c[1]), "+f"(c[2]), "+f"(c[3])
        : "r"(a[0]), "r"(a[1]), "r"(a[2]), "r"(a[3]), "r"(b[0]), "r"(b[1]));
}

__device__ __forceinline__ void lse_merge(float& M, float& S, float m, float s) {
    float nm = fmaxf(M, m);
    if (nm == -CUDART_INF_F) { M = nm; S = 0.f; return; }
    S = S * __expf(M - nm) + s * __expf(m - nm);
    M = nm;
}

// ------------------------- init -------------------------
__global__ void init_kernel() {
    int tid = threadIdx.x;
    if (tid == 0) g_cnt = 0u;
    for (int i = tid; i < HD1; i += blockDim.x) { g_h1buf[0][i] = 0.f; g_h1buf[1][i] = 0.f; }
    for (int i = tid; i < HD2; i += blockDim.x) { g_h2buf[0][i] = 0.f; g_h2buf[1][i] = 0.f; }
}

// ------------------------- U1 = E @ W1e^T + b1 -------------------------
// E[t] = X[idx[t]] (1024 x 300), W1e = W1[:, :300] (1024 x 300)
__global__ void __launch_bounds__(256) u1_kernel(const float* __restrict__ X,
                                                 const float* __restrict__ W1,
                                                 const float* __restrict__ b1,
                                                 const int* __restrict__ idx) {
    __shared__ float sA[20][64];   // [k][t]
    __shared__ float sB[20][64];   // [k][i]
    __shared__ int sidx[64];
    int tid = threadIdx.x;
    int t0 = blockIdx.y * 64, i0 = blockIdx.x * 64;
    if (tid < 64) sidx[tid] = idx[t0 + tid];
    __syncthreads();
    float acc[4][4];
#pragma unroll
    for (int a = 0; a < 4; ++a)
#pragma unroll
        for (int b = 0; b < 4; ++b) acc[a][b] = 0.f;
    int tx = tid & 15, ty = tid >> 4;
    for (int kc = 0; kc < 15; ++kc) {
        int k0 = kc * 20;
        for (int i = tid; i < 1280; i += 256) {
            int k = i >> 6, m = i & 63;
            sA[k][m] = X[(long)sidx[m] * DIM + k0 + k];
            sB[k][m] = W1[(long)(i0 + m) * (DIM + HD1) + k0 + k];
        }
        __syncthreads();
#pragma unroll
        for (int k = 0; k < 20; ++k) {
            float a[4], b[4];
#pragma unroll
            for (int e = 0; e < 4; ++e) { a[e] = sA[k][ty * 4 + e]; b[e] = sB[k][tx * 4 + e]; }
#pragma unroll
            for (int ii = 0; ii < 4; ++ii)
#pragma unroll
                for (int jj = 0; jj < 4; ++jj) acc[ii][jj] += a[ii] * b[jj];
        }
        __syncthreads();
    }
#pragma unroll
    for (int ii = 0; ii < 4; ++ii)
#pragma unroll
        for (int jj = 0; jj < 4; ++jj) {
            int t = t0 + ty * 4 + ii, n = i0 + tx * 4 + jj;
            g_U1[t * HD1 + n] = acc[ii][jj] + b1[n];
        }
}

// ------------------------- persistent RNN core -------------------------
// CTA c owns W1h rows {c + 148q, q<7} and W2 rows {c + 148q, q<4}.
// Thread (warp w, lane l) owns column slice j = w*128 + l + 32*jj (jj<4),
// weights held in registers. One grid barrier per round, rounds r=0..1024:
//   r<1024: h1(r) = LR(W1h @ h1(r-1) + U1[r])
//   r>=1  : h2(r-1) = LR(W2[:, :1024] @ h1(r-1) + W2[:, 1024:] @ h2(r-2) + b2)
__global__ void __launch_bounds__(256) rnn_kernel(const float* __restrict__ W1,
                                                  const float* __restrict__ W2,
                                                  const float* __restrict__ b2) {
    __shared__ float sP1[56];   // [q][warp]
    __shared__ float sP2[32];
    __shared__ float sB2[4];
    int tid = threadIdx.x, c = blockIdx.x;
    int w = tid >> 5, lane = tid & 31;
    int jb = (w << 7) + lane;

    float w1r[4][7], w2a[4][4], w2b[4][4];
#pragma unroll
    for (int q = 0; q < 7; ++q) {
        int row = c + 148 * q;
        bool v = row < HD1;
        const float* p = W1 + (long)(v ? row : 0) * (DIM + HD1) + DIM + jb;
#pragma unroll
        for (int jj = 0; jj < 4; ++jj) w1r[jj][q] = v ? p[jj * 32] : 0.f;
    }
#pragma unroll
    for (int q = 0; q < 4; ++q) {
        int row = c + 148 * q;
        bool v = row < HD2;
        const float* p = W2 + (long)(v ? row : 0) * (HD1 + HD2);
#pragma unroll
        for (int jj = 0; jj < 4; ++jj) {
            w2a[jj][q] = v ? p[jb + jj * 32] : 0.f;
            w2b[jj][q] = (v && w < 4) ? p[HD1 + jb + jj * 32] : 0.f;
        }
    }
    if (tid < 4) {
        int row = c + 148 * tid;
        sB2[tid] = (row < HD2) ? b2[row] : 0.f;
    }
    __syncthreads();

    for (int r = 0; r <= T_STEPS; ++r) {
        const float* h1p = g_h1buf[(r + 1) & 1];   // h1(r-1)
        const float* h2p = g_h2buf[r & 1];          // h2(r-2)

        float p1[7] = {0,0,0,0,0,0,0};
        float p2[4] = {0,0,0,0};
        if (r < T_STEPS || r >= 1) {
#pragma unroll
            for (int jj = 0; jj < 4; ++jj) {
                float h = h1p[jb + jj * 32];
                if (r < T_STEPS) {
#pragma unroll
                    for (int q = 0; q < 7; ++q) p1[q] += w1r[jj][q] * h;
                }
                if (r >= 1) {
#pragma unroll
                    for (int q = 0; q < 4; ++q) p2[q] += w2a[jj][q] * h;
                }
            }
        }
        if (r >= 1 && w < 4) {
#pragma unroll
            for (int jj = 0; jj < 4; ++jj) {
                float h = h2p[jb + jj * 32];
#pragma unroll
                for (int q = 0; q < 4; ++q) p2[q] += w2b[jj][q] * h;
            }
        }
#pragma unroll
        for (int q = 0; q < 7; ++q)
#pragma unroll
            for (int o = 16; o; o >>= 1) p1[q] += __shfl_xor_sync(~0u, p1[q], o);
#pragma unroll
        for (int q = 0; q < 4; ++q)
#pragma unroll
            for (int o = 16; o; o >>= 1) p2[q] += __shfl_xor_sync(~0u, p2[q], o);
        if (lane == 0) {
#pragma unroll
            for (int q = 0; q < 7; ++q) sP1[q * 8 + w] = p1[q];
#pragma unroll
            for (int q = 0; q < 4; ++q) sP2[q * 8 + w] = p2[q];
        }
        __syncthreads();
        if (r < T_STEPS && tid < 7) {
            int row = c + 148 * tid;
            if (row < HD1) {
                float s = 0.f;
#pragma unroll
                for (int k = 0; k < 8; ++k) s += sP1[tid * 8 + k];
                s += g_U1[r * HD1 + row];
                s = s > 0.f ? s : 0.01f * s;
                g_h1buf[r & 1][row] = s;
            }
        }
        if (r >= 1 && tid >= 32 && tid < 36) {
            int q = tid - 32;
            int row = c + 148 * q;
            if (row < HD2) {
                float s = sB2[q];
#pragma unroll
                for (int k = 0; k < 8; ++k) s += sP2[q * 8 + k];
                s = s > 0.f ? s : 0.01f * s;
                g_h2buf[(r + 1) & 1][row] = s;
                g_h2s[(r - 1) * HD2 + row] = s;
            }
        }
        // ---- grid barrier (monotonic counter, no reset) ----
        __syncthreads();
        if (tid == 0) {
            __threadfence();
            atomicAdd(&g_cnt, 1u);
            unsigned target = (unsigned)(r + 1) * NCTA;
            while (*(volatile unsigned*)&g_cnt < target) __nanosleep(64);
            __threadfence();
        }
        __syncthreads();
    }
}

// ------------------------- logits GEMM (tf32 mma) + partial LSE -------------------------
// out[t][v] = h2s[t] . W[v] + bias[v]; per-(128-row,128-col) tile writes
// streaming (max, sumexp) partials. which: 0=globals, 1=senses.
__global__ void __launch_bounds__(256) logits_kernel(const float* __restrict__ W,
                                                     const float* __restrict__ bias,
                                                     float* __restrict__ out,
                                                     int which) {
    __shared__ __align__(16) float sA[128 * 36];
    __shared__ __align__(16) float sB[128 * 36];
    __shared__ float sBias[128];
    __shared__ float sM[128 * 2], sS[128 * 2];

    const int V = which ? VSENS : VGLOB;
    const int pstr = which ? PSTR_S : PSTR_G;
    float* pmax = which ? g_pmaxS : g_pmaxG;
    float* psum = which ? g_psumS : g_psumG;

    int tid = threadIdx.x;
    int m0 = blockIdx.y * 128;
    int n0 = blockIdx.x * 128;
    int lane = tid & 31, warp = tid >> 5;
    int wm = warp & 3, wn = warp >> 2;

    if (tid < 128) {
        int v = n0 + tid;
        sBias[tid] = (v < V) ? bias[v] : 0.f;
    }

    float c[2][8][4];
#pragma unroll
    for (int mt = 0; mt < 2; ++mt)
#pragma unroll
        for (int nt = 0; nt < 8; ++nt)
#pragma unroll
            for (int e = 0; e < 4; ++e) c[mt][nt][e] = 0.f;

    for (int kc = 0; kc < 16; ++kc) {
        int k0 = kc * 32;
#pragma unroll
        for (int p = 0; p < 4; ++p) {
            int f = tid + p * 256;
            int row = f >> 3, kq = f & 7;
            float4 va = *(const float4*)(&g_h2s[(long)(m0 + row) * HD2 + k0 + kq * 4]);
            va.x = to_tf32(va.x); va.y = to_tf32(va.y); va.z = to_tf32(va.z); va.w = to_tf32(va.w);
            *(float4*)(&sA[row * 36 + kq * 4]) = va;
            int vr = n0 + row;
            float4 vb = make_float4(0.f, 0.f, 0.f, 0.f);
            if (vr < V) vb = *(const float4*)(&W[(long)vr * HD2 + k0 + kq * 4]);
            vb.x = to_tf32(vb.x); vb.y = to_tf32(vb.y); vb.z = to_tf32(vb.z); vb.w = to_tf32(vb.w);
            *(float4*)(&sB[row * 36 + kq * 4]) = vb;
        }
        __syncthreads();
#pragma unroll
        for (int ks = 0; ks < 4; ++ks) {
            int kk = ks * 8;
            uint32_t a[2][4], b[8][2];
            int ar = wm * 32 + (lane >> 2);
            int ac = kk + (lane & 3);
#pragma unroll
            for (int mt = 0; mt < 2; ++mt) {
                const float* base = &sA[(ar + mt * 16) * 36 + ac];
                a[mt][0] = __float_as_uint(base[0]);
                a[mt][1] = __float_as_uint(base[8 * 36]);
                a[mt][2] = __float_as_uint(base[4]);
                a[mt][3] = __float_as_uint(base[8 * 36 + 4]);
            }
            int br = wn * 64 + (lane >> 2);
#pragma unroll
            for (int nt = 0; nt < 8; ++nt) {
                const float* base = &sB[(br + nt * 8) * 36 + ac];
                b[nt][0] = __float_as_uint(base[0]);
                b[nt][1] = __float_as_uint(base[4]);
            }
#pragma unroll
            for (int mt = 0; mt < 2; ++mt)
#pragma unroll
                for (int nt = 0; nt < 8; ++nt) mma_tf32(c[mt][nt], a[mt], b[nt]);
        }
        __syncthreads();
    }

    // epilogue: bias add, store logits, streaming (max, sumexp) partials
    int rbase = wm * 32 + (lane >> 2);
    int cbase = wn * 64 + (lane & 3) * 2;
#pragma unroll
    for (int mt = 0; mt < 2; ++mt)
#pragma unroll
        for (int h = 0; h < 2; ++h) {
            int rr = rbase + mt * 16 + h * 8;
            long t = m0 + rr;
            float xs[16];
            float M = -CUDART_INF_F;
#pragma unroll
            for (int nt = 0; nt < 8; ++nt)
#pragma unroll
                for (int e = 0; e < 2; ++e) {
                    int cc = cbase + nt * 8 + e;
                    int v = n0 + cc;
                    float x = -CUDART_INF_F;
                    if (v < V) {
                        x = c[mt][nt][h * 2 + e] + sBias[cc];
                        out[t * V + v] = x;
                        M = fmaxf(M, x);
                    }
                    xs[nt * 2 + e] = x;
                }
            float S = 0.f;
#pragma unroll
            for (int i = 0; i < 16; ++i)
                if (xs[i] != -CUDART_INF_F) S += __expf(xs[i] - M);
#pragma unroll
            for (int o = 1; o <= 2; o <<= 1) {
                float m2 = __shfl_xor_sync(~0u, M, o);
                float s2 = __shfl_xor_sync(~0u, S, o);
                lse_merge(M, S, m2, s2);
            }
            if ((lane & 3) == 0) { sM[rr * 2 + wn] = M; sS[rr * 2 + wn] = S; }
        }
    __syncthreads();
    if (tid < 128) {
        float M = sM[tid * 2], S = sS[tid * 2];
        lse_merge(M, S, sM[tid * 2 + 1], sS[tid * 2 + 1]);
        long t = m0 + tid;
        pmax[t * pstr + blockIdx.x] = M;
        psum[t * pstr + blockIdx.x] = S;
    }
}

// ------------------------- per-row LSE reduction -------------------------
__global__ void lse_kernel() {
    int t = blockIdx.x;
    int which = blockIdx.y;
    const float* pm = which ? g_pmaxS : g_pmaxG;
    const float* ps = which ? g_psumS : g_psumG;
    int nb = which ? TILES_S : TILES_G;
    int pstr = which ? PSTR_S : PSTR_G;
    float M = -CUDART_INF_F, S = 0.f;
    for (int i = threadIdx.x; i < nb; i += 128)
        lse_merge(M, S, pm[(long)t * pstr + i], ps[(long)t * pstr + i]);
#pragma unroll
    for (int o = 16; o; o >>= 1) {
        float m2 = __shfl_xor_sync(~0u, M, o);
        float s2 = __shfl_xor_sync(~0u, S, o);
        lse_merge(M, S, m2, s2);
    }
    __shared__ float sm_[4], ss_[4];
    int w = threadIdx.x >> 5;
    if ((threadIdx.x & 31) == 0) { sm_[w] = M; ss_[w] = S; }
    __syncthreads();
    if (threadIdx.x == 0) {
        for (int k = 1; k < 4; ++k) lse_merge(M, S, sm_[k], ss_[k]);
        float lse = M + logf(S);
        if (which) g_lseS[t] = lse; else g_lseG[t] = lse;
    }
}

// ------------------------- in-place logp = logit - lse -------------------------
__global__ void sub_kernel(float* __restrict__ base, int which, int V, int total4) {
    const float* lse = which ? g_lseS : g_lseG;
    int i = blockIdx.x * blockDim.x + threadIdx.x;
    int stride = gridDim.x * blockDim.x;
    float4* b4 = (float4*)base;
    for (; i < total4; i += stride) {
        float4 v = b4[i];
        int t = (int)(((long)i * 4) / V);
        float l = lse[t];
        v.x -= l; v.y -= l; v.z -= l; v.w -= l;
        b4[i] = v;
    }
}

// ------------------------- launcher -------------------------
extern "C" void kernel_launch(void* const* d_in, const int* in_sizes, int n_in,
                              void* d_out, int out_size) {
    const float* X  = (const float*)d_in[0];
    const float* W1 = (const float*)d_in[1];
    const float* b1 = (const float*)d_in[2];
    const float* W2 = (const float*)d_in[3];
    const float* b2 = (const float*)d_in[4];
    const float* Wg = (const float*)d_in[5];
    const float* bg = (const float*)d_in[6];
    const float* Ws = (const float*)d_in[7];
    const float* bs = (const float*)d_in[8];
    const int*  idx = (const int*)d_in[9];
    float* outG = (float*)d_out;
    float* outS = outG + (size_t)T_STEPS * VGLOB;

    init_kernel<<<1, 256>>>();
    u1_kernel<<<dim3(16, 16), 256>>>(X, W1, b1, idx);
    rnn_kernel<<<NCTA, 256>>>(W1, W2, b2);
    logits_kernel<<<dim3(TILES_G, 8), 256>>>(Wg, bg, outG, 0);
    logits_kernel<<<dim3(TILES_S, 8), 256>>>(Ws, bs, outS, 1);
    lse_kernel<<<dim3(T_STEPS, 2), 128>>>();
    sub_kernel<<<1184, 256>>>(outG, 0, VGLOB, T_STEPS * VGLOB / 4);
    sub_kernel<<<1184, 256>>>(outS, 1, VSENS, T_STEPS * VSENS / 4);
}

// round 4
// speedup vs baseline: 1.1453x; 1.1453x over previous
#include <cuda_runtime.h>
#include <cuda_bf16.h>
#include <cstdint>
#include <math_constants.h>

#define T_STEPS 1024
#define DIM     300
#define HD1     1024
#define HD2     512
#define VGLOB   50000
#define VSENS   25000
#define NCTA    148

#define TILES_G 391
#define TILES_S 196
#define PSTR_G  392
#define PSTR_S  200

// ------------------------- device scratch -------------------------
__device__ __align__(16) float g_U1[T_STEPS * HD1];
__device__ __align__(16) float g_h1buf[2][HD1];
__device__ __align__(16) float g_h2buf[2][HD2];
__device__ unsigned g_cnt;
__device__ float g_pmaxG[T_STEPS * PSTR_G];
__device__ float g_psumG[T_STEPS * PSTR_G];
__device__ float g_pmaxS[T_STEPS * PSTR_S];
__device__ float g_psumS[T_STEPS * PSTR_S];
__device__ float g_lseG[T_STEPS];
__device__ float g_lseS[T_STEPS];
// bf16 operands for the logits GEMM
__device__ __align__(16) uint16_t g_h2sb[T_STEPS * HD2];
__device__ __align__(16) uint16_t g_Wgb[(size_t)VGLOB * HD2];
__device__ __align__(16) uint16_t g_Wsb[(size_t)VSENS * HD2];

// ------------------------- helpers -------------------------
__device__ __forceinline__ void red_release(unsigned* p, unsigned v) {
    asm volatile("red.release.gpu.global.add.u32 [%0], %1;" :: "l"(p), "r"(v) : "memory");
}
__device__ __forceinline__ unsigned ld_acquire(const unsigned* p) {
    unsigned v;
    asm volatile("ld.acquire.gpu.global.u32 %0, [%1];" : "=r"(v) : "l"(p) : "memory");
    return v;
}

__device__ __forceinline__ void mma_bf16(float c[4], const uint32_t a[4], const uint32_t b[2]) {
    asm volatile(
        "mma.sync.aligned.m16n8k16.row.col.f32.bf16.bf16.f32 "
        "{%0,%1,%2,%3}, {%4,%5,%6,%7}, {%8,%9}, {%0,%1,%2,%3};"
        : "+f"(c[0]), "+f"(c[1]), "+f"(c[2]), "+f"(c[3])
        : "r"(a[0]), "r"(a[1]), "r"(a[2]), "r"(a[3]), "r"(b[0]), "r"(b[1]));
}

__device__ __forceinline__ void cp_async16(void* dst_smem, const void* src, int src_bytes) {
    uint32_t d = (uint32_t)__cvta_generic_to_shared(dst_smem);
    asm volatile("cp.async.cg.shared.global [%0], [%1], 16, %2;"
                 :: "r"(d), "l"(src), "r"(src_bytes));
}
__device__ __forceinline__ void cp_commit() { asm volatile("cp.async.commit_group;"); }
template <int N>
__device__ __forceinline__ void cp_wait() { asm volatile("cp.async.wait_group %0;" :: "n"(N)); }

__device__ __forceinline__ void lse_merge(float& M, float& S, float m, float s) {
    float nm = fmaxf(M, m);
    if (nm == -CUDART_INF_F) { M = nm; S = 0.f; return; }
    S = S * __expf(M - nm) + s * __expf(m - nm);
    M = nm;
}

__device__ __forceinline__ uint32_t pack_bf16(float a, float b) {
    __nv_bfloat16 ba = __float2bfloat16(a), bb = __float2bfloat16(b);
    return (uint32_t)reinterpret_cast<unsigned short&>(ba) |
           ((uint32_t)reinterpret_cast<unsigned short&>(bb) << 16);
}

// ------------------------- init -------------------------
__global__ void init_kernel() {
    int tid = threadIdx.x;
    if (tid == 0) g_cnt = 0u;
    for (int i = tid; i < HD1; i += blockDim.x) { g_h1buf[0][i] = 0.f; g_h1buf[1][i] = 0.f; }
    for (int i = tid; i < HD2; i += blockDim.x) { g_h2buf[0][i] = 0.f; g_h2buf[1][i] = 0.f; }
}

// ------------------------- fp32 -> bf16 weight conversion -------------------------
__global__ void convert_kernel(const float* __restrict__ src, uint16_t* __restrict__ dst, int n4) {
    int i = blockIdx.x * blockDim.x + threadIdx.x;
    int stride = gridDim.x * blockDim.x;
    uint32_t* d32 = (uint32_t*)dst;
    const float4* s4 = (const float4*)src;
    for (; i < n4; i += stride) {
        float4 v = s4[i];
        d32[2 * i]     = pack_bf16(v.x, v.y);
        d32[2 * i + 1] = pack_bf16(v.z, v.w);
    }
}

// ------------------------- U1 = E @ W1e^T + b1 -------------------------
__global__ void __launch_bounds__(256) u1_kernel(const float* __restrict__ X,
                                                 const float* __restrict__ W1,
                                                 const float* __restrict__ b1,
                                                 const int* __restrict__ idx) {
    __shared__ float sA[20][64];
    __shared__ float sB[20][64];
    __shared__ int sidx[64];
    int tid = threadIdx.x;
    int t0 = blockIdx.y * 64, i0 = blockIdx.x * 64;
    if (tid < 64) sidx[tid] = idx[t0 + tid];
    __syncthreads();
    float acc[4][4];
#pragma unroll
    for (int a = 0; a < 4; ++a)
#pragma unroll
        for (int b = 0; b < 4; ++b) acc[a][b] = 0.f;
    int tx = tid & 15, ty = tid >> 4;
    for (int kc = 0; kc < 15; ++kc) {
        int k0 = kc * 20;
        for (int i = tid; i < 1280; i += 256) {
            int k = i >> 6, m = i & 63;
            sA[k][m] = X[(long)sidx[m] * DIM + k0 + k];
            sB[k][m] = W1[(long)(i0 + m) * (DIM + HD1) + k0 + k];
        }
        __syncthreads();
#pragma unroll
        for (int k = 0; k < 20; ++k) {
            float a[4], b[4];
#pragma unroll
            for (int e = 0; e < 4; ++e) { a[e] = sA[k][ty * 4 + e]; b[e] = sB[k][tx * 4 + e]; }
#pragma unroll
            for (int ii = 0; ii < 4; ++ii)
#pragma unroll
                for (int jj = 0; jj < 4; ++jj) acc[ii][jj] += a[ii] * b[jj];
        }
        __syncthreads();
    }
#pragma unroll
    for (int ii = 0; ii < 4; ++ii)
#pragma unroll
        for (int jj = 0; jj < 4; ++jj) {
            int t = t0 + ty * 4 + ii, n = i0 + tx * 4 + jj;
            g_U1[t * HD1 + n] = acc[ii][jj] + b1[n];
        }
}

// ------------------------- persistent RNN core -------------------------
// CTA c owns W1h rows {c + 148q, q<7} and W2 rows {c + 148q, q<4}; weights in
// registers. One grid barrier per round via red.release / ld.acquire on a
// monotonic counter. All h-state through L2 (__ldcg/__stcg) — no L1 staleness,
// no gpu-scope fences (no CCTL.IVALL).
__global__ void __launch_bounds__(256) rnn_kernel(const float* __restrict__ W1,
                                                  const float* __restrict__ W2,
                                                  const float* __restrict__ b2) {
    __shared__ float sP1[56];
    __shared__ float sP2[32];
    __shared__ float sB2[4];
    int tid = threadIdx.x, c = blockIdx.x;
    int w = tid >> 5, lane = tid & 31;
    int jb = (w << 7) + lane;

    float w1r[4][7], w2a[4][4], w2b[4][4];
#pragma unroll
    for (int q = 0; q < 7; ++q) {
        int row = c + 148 * q;
        bool v = row < HD1;
        const float* p = W1 + (long)(v ? row : 0) * (DIM + HD1) + DIM + jb;
#pragma unroll
        for (int jj = 0; jj < 4; ++jj) w1r[jj][q] = v ? p[jj * 32] : 0.f;
    }
#pragma unroll
    for (int q = 0; q < 4; ++q) {
        int row = c + 148 * q;
        bool v = row < HD2;
        const float* p = W2 + (long)(v ? row : 0) * (HD1 + HD2);
#pragma unroll
        for (int jj = 0; jj < 4; ++jj) {
            w2a[jj][q] = v ? p[jb + jj * 32] : 0.f;
            w2b[jj][q] = (v && w < 4) ? p[HD1 + jb + jj * 32] : 0.f;
        }
    }
    if (tid < 4) {
        int row = c + 148 * tid;
        sB2[tid] = (row < HD2) ? b2[row] : 0.f;
    }
    __syncthreads();

    for (int r = 0; r <= T_STEPS; ++r) {
        const float* h1p = g_h1buf[(r + 1) & 1];   // h1(r-1)
        const float* h2p = g_h2buf[r & 1];          // h2(r-2)

        // prefetch U1 for the writer threads
        float u1v = 0.f;
        if (r < T_STEPS && tid < 7) {
            int row = c + 148 * tid;
            if (row < HD1) u1v = __ldg(&g_U1[r * HD1 + row]);
        }

        float p1[7] = {0, 0, 0, 0, 0, 0, 0};
        float p2[4] = {0, 0, 0, 0};
#pragma unroll
        for (int jj = 0; jj < 4; ++jj) {
            float h = __ldcg(&h1p[jb + jj * 32]);
            if (r < T_STEPS) {
#pragma unroll
                for (int q = 0; q < 7; ++q) p1[q] += w1r[jj][q] * h;
            }
            if (r >= 1) {
#pragma unroll
                for (int q = 0; q < 4; ++q) p2[q] += w2a[jj][q] * h;
            }
        }
        if (r >= 1 && w < 4) {
#pragma unroll
            for (int jj = 0; jj < 4; ++jj) {
                float h = __ldcg(&h2p[jb + jj * 32]);
#pragma unroll
                for (int q = 0; q < 4; ++q) p2[q] += w2b[jj][q] * h;
            }
        }
#pragma unroll
        for (int q = 0; q < 7; ++q)
#pragma unroll
            for (int o = 16; o; o >>= 1) p1[q] += __shfl_xor_sync(~0u, p1[q], o);
#pragma unroll
        for (int q = 0; q < 4; ++q)
#pragma unroll
            for (int o = 16; o; o >>= 1) p2[q] += __shfl_xor_sync(~0u, p2[q], o);
        if (lane == 0) {
#pragma unroll
            for (int q = 0; q < 7; ++q) sP1[q * 8 + w] = p1[q];
#pragma unroll
            for (int q = 0; q < 4; ++q) sP2[q * 8 + w] = p2[q];
        }
        __syncthreads();

        if (w < 2) {
            if (r < T_STEPS && tid < 7) {
                int row = c + 148 * tid;
                if (row < HD1) {
                    float s = u1v;
#pragma unroll
                    for (int k = 0; k < 8; ++k) s += sP1[tid * 8 + k];
                    s = s > 0.f ? s : 0.01f * s;
                    __stcg(&g_h1buf[r & 1][row], s);
                }
            }
            if (r >= 1 && tid >= 32 && tid < 36) {
                int q = tid - 32;
                int row = c + 148 * q;
                if (row < HD2) {
                    float s = sB2[q];
#pragma unroll
                    for (int k = 0; k < 8; ++k) s += sP2[q * 8 + k];
                    s = s > 0.f ? s : 0.01f * s;
                    __stcg(&g_h2buf[(r + 1) & 1][row], s);
                    __nv_bfloat16 b = __float2bfloat16(s);
                    g_h2sb[(r - 1) * HD2 + row] = reinterpret_cast<unsigned short&>(b);
                }
            }
            asm volatile("bar.sync 1, 64;" ::: "memory");  // warps 0-1: stores done
            if (tid == 0) red_release(&g_cnt, 1u);
        }
        if (tid == 0) {
            unsigned target = (unsigned)(r + 1) * NCTA;
            while (ld_acquire(&g_cnt) < target) {}
        }
        __syncthreads();
    }
}

// ------------------------- logits GEMM (bf16 mma, cp.async pipelined) -------------------------
__global__ void __launch_bounds__(256) logits_kernel(const uint16_t* __restrict__ Wb,
                                                     const float* __restrict__ bias,
                                                     float* __restrict__ out,
                                                     int which) {
    __shared__ __align__(16) uint16_t sA[2][128 * 40];
    __shared__ __align__(16) uint16_t sB[2][128 * 40];
    __shared__ float sBias[128];
    __shared__ float sM[128 * 2], sS[128 * 2];

    const int V = which ? VSENS : VGLOB;
    const int pstr = which ? PSTR_S : PSTR_G;
    float* pmax = which ? g_pmaxS : g_pmaxG;
    float* psum = which ? g_psumS : g_psumG;

    int tid = threadIdx.x;
    int m0 = blockIdx.y * 128;
    int n0 = blockIdx.x * 128;
    int lane = tid & 31, warp = tid >> 5;
    int wm = warp & 3, wn = warp >> 2;

    if (tid < 128) {
        int v = n0 + tid;
        sBias[tid] = (v < V) ? bias[v] : 0.f;
    }

    float c[2][8][4];
#pragma unroll
    for (int mt = 0; mt < 2; ++mt)
#pragma unroll
        for (int nt = 0; nt < 8; ++nt)
#pragma unroll
            for (int e = 0; e < 4; ++e) c[mt][nt][e] = 0.f;

    // issue one K-chunk (32 bf16) into stage s
    auto issue = [&](int kc, int s) {
        int k0 = kc * 32;
#pragma unroll
        for (int p = 0; p < 2; ++p) {
            int f = tid + p * 256;        // 0..511
            int row = f >> 2, seg = f & 3;
            cp_async16(&sA[s][row * 40 + seg * 8],
                       &g_h2sb[(long)(m0 + row) * HD2 + k0 + seg * 8], 16);
            int vr = n0 + row;
            int srow = vr < V ? vr : 0;
            cp_async16(&sB[s][row * 40 + seg * 8],
                       &Wb[(long)srow * HD2 + k0 + seg * 8], vr < V ? 16 : 0);
        }
        cp_commit();
    };

    issue(0, 0);
    for (int kc = 0; kc < 16; ++kc) {
        if (kc + 1 < 16) { issue(kc + 1, (kc + 1) & 1); cp_wait<1>(); }
        else             { cp_wait<0>(); }
        __syncthreads();
        const uint16_t* pA = sA[kc & 1];
        const uint16_t* pB = sB[kc & 1];
#pragma unroll
        for (int ks = 0; ks < 2; ++ks) {
            int kk = ks * 16;
            uint32_t a[2][4], b[8][2];
            int ar = wm * 32 + (lane >> 2);
            int ac = kk + (lane & 3) * 2;
#pragma unroll
            for (int mt = 0; mt < 2; ++mt) {
                const uint16_t* base = &pA[(ar + mt * 16) * 40 + ac];
                a[mt][0] = *(const uint32_t*)(base);
                a[mt][1] = *(const uint32_t*)(base + 8 * 40);
                a[mt][2] = *(const uint32_t*)(base + 8);
                a[mt][3] = *(const uint32_t*)(base + 8 * 40 + 8);
            }
            int br = wn * 64 + (lane >> 2);
#pragma unroll
            for (int nt = 0; nt < 8; ++nt) {
                const uint16_t* base = &pB[(br + nt * 8) * 40 + ac];
                b[nt][0] = *(const uint32_t*)(base);
                b[nt][1] = *(const uint32_t*)(base + 8);
            }
#pragma unroll
            for (int mt = 0; mt < 2; ++mt)
#pragma unroll
                for (int nt = 0; nt < 8; ++nt) mma_bf16(c[mt][nt], a[mt], b[nt]);
        }
        __syncthreads();
    }

    // epilogue: bias add, store logits, streaming (max, sumexp) partials
    int rbase = wm * 32 + (lane >> 2);
    int cbase = wn * 64 + (lane & 3) * 2;
#pragma unroll
    for (int mt = 0; mt < 2; ++mt)
#pragma unroll
        for (int h = 0; h < 2; ++h) {
            int rr = rbase + mt * 16 + h * 8;
            long t = m0 + rr;
            float xs[16];
            float M = -CUDART_INF_F;
#pragma unroll
            for (int nt = 0; nt < 8; ++nt)
#pragma unroll
                for (int e = 0; e < 2; ++e) {
                    int cc = cbase + nt * 8 + e;
                    int v = n0 + cc;
                    float x = -CUDART_INF_F;
                    if (v < V) {
                        x = c[mt][nt][h * 2 + e] + sBias[cc];
                        out[t * V + v] = x;
                        M = fmaxf(M, x);
                    }
                    xs[nt * 2 + e] = x;
                }
            float S = 0.f;
#pragma unroll
            for (int i = 0; i < 16; ++i)
                if (xs[i] != -CUDART_INF_F) S += __expf(xs[i] - M);
#pragma unroll
            for (int o = 1; o <= 2; o <<= 1) {
                float m2 = __shfl_xor_sync(~0u, M, o);
                float s2 = __shfl_xor_sync(~0u, S, o);
                lse_merge(M, S, m2, s2);
            }
            if ((lane & 3) == 0) { sM[rr * 2 + wn] = M; sS[rr * 2 + wn] = S; }
        }
    __syncthreads();
    if (tid < 128) {
        float M = sM[tid * 2], S = sS[tid * 2];
        lse_merge(M, S, sM[tid * 2 + 1], sS[tid * 2 + 1]);
        long t = m0 + tid;
        pmax[t * pstr + blockIdx.x] = M;
        psum[t * pstr + blockIdx.x] = S;
    }
}

// ------------------------- per-row LSE reduction -------------------------
__global__ void lse_kernel() {
    int t = blockIdx.x;
    int which = blockIdx.y;
    const float* pm = which ? g_pmaxS : g_pmaxG;
    const float* ps = which ? g_psumS : g_psumG;
    int nb = which ? TILES_S : TILES_G;
    int pstr = which ? PSTR_S : PSTR_G;
    float M = -CUDART_INF_F, S = 0.f;
    for (int i = threadIdx.x; i < nb; i += 128)
        lse_merge(M, S, pm[(long)t * pstr + i], ps[(long)t * pstr + i]);
#pragma unroll
    for (int o = 16; o; o >>= 1) {
        float m2 = __shfl_xor_sync(~0u, M, o);
        float s2 = __shfl_xor_sync(~0u, S, o);
        lse_merge(M, S, m2, s2);
    }
    __shared__ float sm_[4], ss_[4];
    int w = threadIdx.x >> 5;
    if ((threadIdx.x & 31) == 0) { sm_[w] = M; ss_[w] = S; }
    __syncthreads();
    if (threadIdx.x == 0) {
        for (int k = 1; k < 4; ++k) lse_merge(M, S, sm_[k], ss_[k]);
        float lse = M + logf(S);
        if (which) g_lseS[t] = lse; else g_lseG[t] = lse;
    }
}

// ------------------------- in-place logp = logit - lse -------------------------
__global__ void sub_kernel(float* __restrict__ base, int which, int V, int total4) {
    const float* lse = which ? g_lseS : g_lseG;
    int i = blockIdx.x * blockDim.x + threadIdx.x;
    int stride = gridDim.x * blockDim.x;
    float4* b4 = (float4*)base;
    for (; i < total4; i += stride) {
        float4 v = b4[i];
        int t = (int)(((long)i * 4) / V);
        float l = lse[t];
        v.x -= l; v.y -= l; v.z -= l; v.w -= l;
        b4[i] = v;
    }
}

// ------------------------- launcher -------------------------
extern "C" void kernel_launch(void* const* d_in, const int* in_sizes, int n_in,
                              void* d_out, int out_size) {
    const float* X  = (const float*)d_in[0];
    const float* W1 = (const float*)d_in[1];
    const float* b1 = (const float*)d_in[2];
    const float* W2 = (const float*)d_in[3];
    const float* b2 = (const float*)d_in[4];
    const float* Wg = (const float*)d_in[5];
    const float* bg = (const float*)d_in[6];
    const float* Ws = (const float*)d_in[7];
    const float* bs = (const float*)d_in[8];
    const int*  idx = (const int*)d_in[9];
    float* outG = (float*)d_out;
    float* outS = outG + (size_t)T_STEPS * VGLOB;

    uint16_t* wgb; cudaGetSymbolAddress((void**)&wgb, g_Wgb);
    uint16_t* wsb; cudaGetSymbolAddress((void**)&wsb, g_Wsb);

    init_kernel<<<1, 256>>>();
    convert_kernel<<<2048, 256>>>(Wg, wgb, VGLOB * HD2 / 4);
    convert_kernel<<<2048, 256>>>(Ws, wsb, VSENS * HD2 / 4);
    u1_kernel<<<dim3(16, 16), 256>>>(X, W1, b1, idx);
    rnn_kernel<<<NCTA, 256>>>(W1, W2, b2);
    logits_kernel<<<dim3(TILES_G, 8), 256>>>(wgb, bg, outG, 0);
    logits_kernel<<<dim3(TILES_S, 8), 256>>>(wsb, bs, outS, 1);
    lse_kernel<<<dim3(T_STEPS, 2), 128>>>();
    sub_kernel<<<1184, 256>>>(outG, 0, VGLOB, T_STEPS * VGLOB / 4);
    sub_kernel<<<1184, 256>>>(outS, 1, VSENS, T_STEPS * VSENS / 4);
}